// round 5
// baseline (speedup 1.0000x reference)
#include <cuda_runtime.h>
#include <math.h>

#define HEADS 8
#define HW 64
#define D 32
#define NTOK 4096
#define DIMX 256
#define INCDIM 768

// ---------------- scratch (static device globals; no allocation) -------------
__device__ float g_Q[HEADS * NTOK * D];                 // 4 MB
__device__ float g_K[HEADS * NTOK * D];                 // 4 MB
__device__ float g_V[HEADS * NTOK * D];                 // 4 MB
__device__ float g_U[(size_t)HEADS * HW * HW * D * D];  // 134 MB row-cumsum of k (x) v
__device__ float g_Kc[HEADS * HW * HW * D];             // 4 MB row-cumsum of k

// ---------------- packed fp32x2 FMA (exact fp32, 2x issue density) -----------
__device__ __forceinline__ void ffma2(float2& d, float2 a, float2 b) {
    asm("fma.rn.f32x2 %0, %1, %2, %0;"
        : "+l"(*reinterpret_cast<unsigned long long*>(&d))
        : "l"(*reinterpret_cast<unsigned long long*>(&a)),
          "l"(*reinterpret_cast<unsigned long long*>(&b)));
}

// ---------------- Kernel 1: fused QKV GEMM + ELU epilogue --------------------
// C[4096 x 768] = x @ [wq|wk|wv]. Tile 64x128, BK=32, 128 thr, 8x8 per thread.
__global__ __launch_bounds__(128) void k_qkv(const float* __restrict__ x,
                                             const float* __restrict__ wq,
                                             const float* __restrict__ wk,
                                             const float* __restrict__ wv) {
    __shared__ float As[32 * 64];    // [kk][m]
    __shared__ float Bs[32 * 128];   // [kk][n]
    const int row0 = blockIdx.x * 64;
    const int col0g = blockIdx.y * 128;     // 0..767
    const int part = col0g >> 8;            // 0=q 1=k 2=v
    const int col0 = col0g & 255;
    const float* W = (part == 0) ? wq : (part == 1) ? wk : wv;
    const int tid = threadIdx.x;
    const int tx = tid & 15, ty = tid >> 4;

    float4 pa[4];
    float4 pb[8];
#pragma unroll
    for (int i = 0; i < 4; i++) {
        int l = tid + i * 128;
        int m = l & 63, kq = l >> 6;
        pa[i] = *(const float4*)&x[(size_t)(row0 + m) * DIMX + kq * 4];
    }
#pragma unroll
    for (int i = 0; i < 8; i++) {
        int l = tid + i * 128;
        int n4 = l & 31, kk = l >> 5;
        pb[i] = *(const float4*)&W[(size_t)kk * DIMX + col0 + n4 * 4];
    }

    float2 acc[8][4] = {};
    for (int k0 = 0; k0 < DIMX; k0 += 32) {
#pragma unroll
        for (int i = 0; i < 4; i++) {
            int l = tid + i * 128;
            int m = l & 63, kq = l >> 6;
            As[(kq * 4 + 0) * 64 + m] = pa[i].x;
            As[(kq * 4 + 1) * 64 + m] = pa[i].y;
            As[(kq * 4 + 2) * 64 + m] = pa[i].z;
            As[(kq * 4 + 3) * 64 + m] = pa[i].w;
        }
#pragma unroll
        for (int i = 0; i < 8; i++) {
            int l = tid + i * 128;
            int n4 = l & 31, kk = l >> 5;
            *(float4*)&Bs[kk * 128 + n4 * 4] = pb[i];
        }
        __syncthreads();
        if (k0 + 32 < DIMX) {
#pragma unroll
            for (int i = 0; i < 4; i++) {
                int l = tid + i * 128;
                int m = l & 63, kq = l >> 6;
                pa[i] = *(const float4*)&x[(size_t)(row0 + m) * DIMX + k0 + 32 + kq * 4];
            }
#pragma unroll
            for (int i = 0; i < 8; i++) {
                int l = tid + i * 128;
                int n4 = l & 31, kk = l >> 5;
                pb[i] = *(const float4*)&W[(size_t)(k0 + 32 + kk) * DIMX + col0 + n4 * 4];
            }
        }
#pragma unroll
        for (int kk = 0; kk < 32; kk++) {
            float4 a0 = *(float4*)&As[kk * 64 + ty * 8];
            float4 a1 = *(float4*)&As[kk * 64 + ty * 8 + 4];
            float av[8] = {a0.x, a0.y, a0.z, a0.w, a1.x, a1.y, a1.z, a1.w};
            float2 bv[4];
            bv[0] = *(float2*)&Bs[kk * 128 + tx * 8 + 0];
            bv[1] = *(float2*)&Bs[kk * 128 + tx * 8 + 2];
            bv[2] = *(float2*)&Bs[kk * 128 + tx * 8 + 4];
            bv[3] = *(float2*)&Bs[kk * 128 + tx * 8 + 6];
#pragma unroll
            for (int i = 0; i < 8; i++) {
                float2 a2 = {av[i], av[i]};
#pragma unroll
                for (int j = 0; j < 4; j++) ffma2(acc[i][j], a2, bv[j]);
            }
        }
        __syncthreads();
    }

    float* dst = (part == 0) ? g_Q : (part == 1) ? g_K : g_V;
    const int ccb = col0 + tx * 8;           // 8 consecutive cols, within one head
    const int h = ccb >> 5, e0 = ccb & 31;
#pragma unroll
    for (int i = 0; i < 8; i++) {
        int n = row0 + ty * 8 + i;
        float v[8] = {acc[i][0].x, acc[i][0].y, acc[i][1].x, acc[i][1].y,
                      acc[i][2].x, acc[i][2].y, acc[i][3].x, acc[i][3].y};
        if (part < 2) {
#pragma unroll
            for (int j = 0; j < 8; j++)
                v[j] = (v[j] > 0.f) ? (v[j] + 1.000001f) : (expf(v[j]) + 1e-6f);
        }
        float* p = &dst[((size_t)(h * NTOK + n)) * D + e0];
        *(float4*)p = make_float4(v[0], v[1], v[2], v[3]);
        *(float4*)(p + 4) = make_float4(v[4], v[5], v[6], v[7]);
    }
}

// ---------------- Kernel 2: row-direction cumsums ----------------------------
__global__ __launch_bounds__(256) void k_integral() {
    const int j = blockIdx.x;
    const int h = blockIdx.y;
    __shared__ float ksh[HW * D];
    __shared__ float vsh[HW * D];
    const int tid = threadIdx.x;
#pragma unroll
    for (int r = 0; r < 8; r++) {
        int l = tid + r * 256;
        int i = l >> 5, a = l & 31;
        size_t gi = ((size_t)(h * NTOK + i * HW + j)) * D + a;
        ksh[l] = g_K[gi];
        vsh[l] = g_V[gi];
    }
    __syncthreads();
    const int a = tid >> 3;
    const int b = (tid & 7) * 4;
    float4 acc = make_float4(0.f, 0.f, 0.f, 0.f);
    float kacc = 0.f;
    for (int i = 0; i < HW; i++) {
        float kv = ksh[i * D + a];
        float4 vv = *(const float4*)&vsh[i * D + b];
        acc.x += kv * vv.x; acc.y += kv * vv.y; acc.z += kv * vv.z; acc.w += kv * vv.w;
        *(float4*)&g_U[(((size_t)(h * HW + i)) * HW + j) * (D * D) + tid * 4] = acc;
        if (tid < 32) {
            kacc += ksh[i * D + tid];
            g_Kc[((h * HW + i) * HW + j) * D + tid] = kacc;
        }
    }
}

// ---------------- Kernel 3: bias init ----------------------------------------
__global__ __launch_bounds__(256) void k_bias(const float* __restrict__ bo,
                                              float* __restrict__ out) {
    int idx = blockIdx.x * 256 + threadIdx.x;          // float4 index
    float4 b = *(const float4*)&bo[(idx * 4) & 255];
    *(float4*)&out[(size_t)idx * 4] = b;
}

// ---------------- Kernel 4: windowed sweep + fused output GEMM ---------------
// block = (ii, window, head). Sweep j with double-buffered prefix matrix,
// then epilogue in two 128-col passes: o = num/den ; atomicAdd(out, o @ wo).
__global__ __launch_bounds__(256) void k_attn(const float* __restrict__ wo,
                                              float* __restrict__ out) {
    const int ii = blockIdx.x;
    const int win = blockIdx.y;
    const int h = blockIdx.z;
    const int r = (win == 0) ? 32 : (win == 1) ? 16 : 8;

    __shared__ float qsh[HW * D];        // 8 KB; later reused as o
    __shared__ float Msh[2][D * D];      // 8 KB
    __shared__ float numsh[HW * D];      // 8 KB
    __shared__ float densh[HW];
    __shared__ float pksh[2][D];
    __shared__ float wosh[D * 128];      // 16 KB: half of wo rows' columns

    const int tid = threadIdx.x;
    const int warp = tid >> 5, lane = tid & 31;
    const float* wsrc = wo + ((size_t)(win * DIMX + h * D)) * DIMX;

    // load wo col-half 0 (overlaps sweep; consumed after post-sweep barrier)
#pragma unroll
    for (int i = 0; i < 4; i++) {
        int l = tid + i * 256;               // l = e*32 + c4 ; cols 0..127
        int e = l >> 5, c4 = l & 31;
        *(float4*)&wosh[e * 128 + c4 * 4] = *(const float4*)&wsrc[(size_t)e * DIMX + c4 * 4];
    }
#pragma unroll
    for (int rr = 0; rr < 8; rr++) {
        int l = tid + rr * 256;
        qsh[l] = g_Q[((size_t)(h * NTOK + ii * HW)) * D + l];
        numsh[l] = 0.f;
    }
    *(float4*)&Msh[1][tid * 4] = make_float4(0.f, 0.f, 0.f, 0.f);
    if (tid < 64) densh[tid] = 0.f;
    if (tid < 32) pksh[1][tid] = 0.f;

    const int x2 = min(ii + r, HW - 1);
    const int xl = ii - r - 1;
    const bool hasl = (xl >= 0);
    const float* Uh = g_U + ((size_t)(h * HW + x2)) * HW * (D * D);
    const float* Ul = g_U + ((size_t)(h * HW + max(xl, 0))) * HW * (D * D);
    const float* Kh = g_Kc + (h * HW + x2) * HW * D;
    const float* Kl = g_Kc + (h * HW + max(xl, 0)) * HW * D;

    // prefetch step j=0
    float4 d = *(const float4*)&Uh[tid * 4];
    float kd = (tid < 32) ? Kh[tid] : 0.f;
    if (hasl) {
        float4 dl = *(const float4*)&Ul[tid * 4];
        d.x -= dl.x; d.y -= dl.y; d.z -= dl.z; d.w -= dl.w;
        if (tid < 32) kd -= Kl[tid];
    }
    __syncthreads();

    for (int j = 0; j < HW; j++) {
        const int cur = j & 1, prev = cur ^ 1;
        float4 m = *(float4*)&Msh[prev][tid * 4];
        m.x += d.x; m.y += d.y; m.z += d.z; m.w += d.w;
        *(float4*)&Msh[cur][tid * 4] = m;
        if (tid < 32) pksh[cur][tid] = pksh[prev][tid] + kd;
        if (j < HW - 1) {
            size_t off = (size_t)(j + 1) * (D * D) + tid * 4;
            d = *(const float4*)&Uh[off];
            kd = (tid < 32) ? Kh[(j + 1) * D + tid] : 0.f;
            if (hasl) {
                float4 dl = *(const float4*)&Ul[off];
                d.x -= dl.x; d.y -= dl.y; d.z -= dl.z; d.w -= dl.w;
                if (tid < 32) kd -= Kl[(j + 1) * D + tid];
            }
        }
        __syncthreads();

        const int nplus = (j == HW - 1) ? (r + 1) : ((j >= r) ? 1 : 0);
        const int jjp0  = (j == HW - 1) ? (HW - 1 - r) : (j - r);
        const int hasminus = (j + r + 1 <= HW - 1) ? 1 : 0;
        const int nev = nplus + hasminus;
        for (int e = warp; e < nev; e += 8) {
            int jj; float sgn;
            if (e < nplus) { jj = jjp0 + e; sgn = 1.f; }
            else           { jj = j + r + 1; sgn = -1.f; }
            const float* qrow = &qsh[jj * D];
            float rv = 0.f;
#pragma unroll
            for (int a = 0; a < 32; a++) rv += qrow[a] * Msh[cur][a * 32 + lane];
            numsh[jj * D + lane] += sgn * rv;
            float p = qrow[lane] * pksh[cur][lane];
#pragma unroll
            for (int off = 16; off; off >>= 1) p += __shfl_xor_sync(0xffffffffu, p, off);
            if (lane == 0) densh[jj] += sgn * p;
        }
    }
    __syncthreads();

    // o = num / den  (into qsh, q no longer needed)
#pragma unroll
    for (int rr = 0; rr < 8; rr++) {
        int l = tid + rr * 256;
        int jj = l >> 5;
        qsh[l] = numsh[l] / (densh[jj] + 1e-6f);
    }
    __syncthreads();

    // epilogue GEMM in two column halves: out[ii*64+jj, half*128+c] += o @ wo
    const int jj0 = warp * 8;
#pragma unroll
    for (int half = 0; half < 2; half++) {
        if (half == 1) {
            __syncthreads();   // done reading wosh half 0
#pragma unroll
            for (int i = 0; i < 4; i++) {
                int l = tid + i * 256;
                int e = l >> 5, c4 = l & 31;
                *(float4*)&wosh[e * 128 + c4 * 4] =
                    *(const float4*)&wsrc[(size_t)e * DIMX + 128 + c4 * 4];
            }
            __syncthreads();
        }
        float acc[8][4];
#pragma unroll
        for (int i = 0; i < 8; i++)
#pragma unroll
            for (int m = 0; m < 4; m++) acc[i][m] = 0.f;
#pragma unroll
        for (int e = 0; e < D; e++) {
            float wv[4];
#pragma unroll
            for (int m = 0; m < 4; m++) wv[m] = wosh[e * 128 + lane + m * 32];
#pragma unroll
            for (int i = 0; i < 8; i++) {
                float ov = qsh[(jj0 + i) * D + e];
#pragma unroll
                for (int m = 0; m < 4; m++) acc[i][m] += ov * wv[m];
            }
        }
#pragma unroll
        for (int i = 0; i < 8; i++) {
            float* orow = &out[(size_t)(ii * HW + jj0 + i) * DIMX + half * 128];
#pragma unroll
            for (int m = 0; m < 4; m++)
                atomicAdd(&orow[lane + m * 32], acc[i][m]);
        }
    }
}

// ---------------- launch -----------------------------------------------------
extern "C" void kernel_launch(void* const* d_in, const int* in_sizes, int n_in,
                              void* d_out, int out_size) {
    const float* x  = (const float*)d_in[0];
    const float* wq = (const float*)d_in[1];
    const float* wk = (const float*)d_in[2];
    const float* wv = (const float*)d_in[3];
    const float* wo = (const float*)d_in[4];
    const float* bo = (const float*)d_in[5];
    float* out = (float*)d_out;

    k_qkv<<<dim3(NTOK / 64, INCDIM / 128), 128>>>(x, wq, wk, wv);
    k_integral<<<dim3(HW, HEADS), 256>>>();
    k_bias<<<(NTOK * DIMX / 4) / 256, 256>>>(bo, out);
    k_attn<<<dim3(HW, 3, HEADS), 256>>>(wo, out);
}

// round 6
// speedup vs baseline: 1.3590x; 1.3590x over previous
#include <cuda_runtime.h>
#include <math.h>

#define HEADS 8
#define HW 64
#define D 32
#define NTOK 4096
#define DIMX 256
#define INCDIM 768
#define DEPTH 4

// ---------------- scratch (static device globals; no allocation) -------------
__device__ float g_Q[HEADS * NTOK * D];                 // 4 MB
__device__ float g_K[HEADS * NTOK * D];                 // 4 MB
__device__ float g_V[HEADS * NTOK * D];                 // 4 MB
__device__ float g_U[(size_t)HEADS * HW * HW * D * D];  // 134 MB row-cumsum of k (x) v
__device__ float g_Kc[HEADS * HW * HW * D];             // 4 MB k integral (row, then 2D)
__device__ float g_Cat[(size_t)NTOK * INCDIM];          // 12.6 MB window-output concat

// ---------------- packed fp32x2 FMA (exact fp32, 2x issue density) -----------
__device__ __forceinline__ void ffma2(float2& d, float2 a, float2 b) {
    asm("fma.rn.f32x2 %0, %1, %2, %0;"
        : "+l"(*reinterpret_cast<unsigned long long*>(&d))
        : "l"(*reinterpret_cast<unsigned long long*>(&a)),
          "l"(*reinterpret_cast<unsigned long long*>(&b)));
}

// ---------------- Kernel 1: fused QKV GEMM + ELU epilogue --------------------
__global__ __launch_bounds__(128) void k_qkv(const float* __restrict__ x,
                                             const float* __restrict__ wq,
                                             const float* __restrict__ wk,
                                             const float* __restrict__ wv) {
    __shared__ float As[32 * 64];    // [kk][m]
    __shared__ float Bs[32 * 128];   // [kk][n]
    const int row0 = blockIdx.x * 64;
    const int col0g = blockIdx.y * 128;     // 0..767
    const int part = col0g >> 8;            // 0=q 1=k 2=v
    const int col0 = col0g & 255;
    const float* W = (part == 0) ? wq : (part == 1) ? wk : wv;
    const int tid = threadIdx.x;
    const int tx = tid & 15, ty = tid >> 4;

    float4 pa[4];
    float4 pb[8];
#pragma unroll
    for (int i = 0; i < 4; i++) {
        int l = tid + i * 128;
        int m = l & 63, kq = l >> 6;
        pa[i] = *(const float4*)&x[(size_t)(row0 + m) * DIMX + kq * 4];
    }
#pragma unroll
    for (int i = 0; i < 8; i++) {
        int l = tid + i * 128;
        int n4 = l & 31, kk = l >> 5;
        pb[i] = *(const float4*)&W[(size_t)kk * DIMX + col0 + n4 * 4];
    }

    float2 acc[8][4] = {};
    for (int k0 = 0; k0 < DIMX; k0 += 32) {
#pragma unroll
        for (int i = 0; i < 4; i++) {
            int l = tid + i * 128;
            int m = l & 63, kq = l >> 6;
            As[(kq * 4 + 0) * 64 + m] = pa[i].x;
            As[(kq * 4 + 1) * 64 + m] = pa[i].y;
            As[(kq * 4 + 2) * 64 + m] = pa[i].z;
            As[(kq * 4 + 3) * 64 + m] = pa[i].w;
        }
#pragma unroll
        for (int i = 0; i < 8; i++) {
            int l = tid + i * 128;
            int n4 = l & 31, kk = l >> 5;
            *(float4*)&Bs[kk * 128 + n4 * 4] = pb[i];
        }
        __syncthreads();
        if (k0 + 32 < DIMX) {
#pragma unroll
            for (int i = 0; i < 4; i++) {
                int l = tid + i * 128;
                int m = l & 63, kq = l >> 6;
                pa[i] = *(const float4*)&x[(size_t)(row0 + m) * DIMX + k0 + 32 + kq * 4];
            }
#pragma unroll
            for (int i = 0; i < 8; i++) {
                int l = tid + i * 128;
                int n4 = l & 31, kk = l >> 5;
                pb[i] = *(const float4*)&W[(size_t)(k0 + 32 + kk) * DIMX + col0 + n4 * 4];
            }
        }
#pragma unroll
        for (int kk = 0; kk < 32; kk++) {
            float4 a0 = *(float4*)&As[kk * 64 + ty * 8];
            float4 a1 = *(float4*)&As[kk * 64 + ty * 8 + 4];
            float av[8] = {a0.x, a0.y, a0.z, a0.w, a1.x, a1.y, a1.z, a1.w};
            float2 bv[4];
            bv[0] = *(float2*)&Bs[kk * 128 + tx * 8 + 0];
            bv[1] = *(float2*)&Bs[kk * 128 + tx * 8 + 2];
            bv[2] = *(float2*)&Bs[kk * 128 + tx * 8 + 4];
            bv[3] = *(float2*)&Bs[kk * 128 + tx * 8 + 6];
#pragma unroll
            for (int i = 0; i < 8; i++) {
                float2 a2 = {av[i], av[i]};
#pragma unroll
                for (int j = 0; j < 4; j++) ffma2(acc[i][j], a2, bv[j]);
            }
        }
        __syncthreads();
    }

    float* dst = (part == 0) ? g_Q : (part == 1) ? g_K : g_V;
    const int ccb = col0 + tx * 8;           // 8 consecutive cols, within one head
    const int h = ccb >> 5, e0 = ccb & 31;
#pragma unroll
    for (int i = 0; i < 8; i++) {
        int n = row0 + ty * 8 + i;
        float v[8] = {acc[i][0].x, acc[i][0].y, acc[i][1].x, acc[i][1].y,
                      acc[i][2].x, acc[i][2].y, acc[i][3].x, acc[i][3].y};
        if (part < 2) {
#pragma unroll
            for (int j = 0; j < 8; j++)
                v[j] = (v[j] > 0.f) ? (v[j] + 1.000001f) : (expf(v[j]) + 1e-6f);
        }
        float* p = &dst[((size_t)(h * NTOK + n)) * D + e0];
        *(float4*)p = make_float4(v[0], v[1], v[2], v[3]);
        *(float4*)(p + 4) = make_float4(v[4], v[5], v[6], v[7]);
    }
}

// ---------------- Kernel 2: row-direction cumsums ----------------------------
__global__ __launch_bounds__(256) void k_integral() {
    const int j = blockIdx.x;
    const int h = blockIdx.y;
    __shared__ float ksh[HW * D];
    __shared__ float vsh[HW * D];
    const int tid = threadIdx.x;
#pragma unroll
    for (int r = 0; r < 8; r++) {
        int l = tid + r * 256;
        int i = l >> 5, a = l & 31;
        size_t gi = ((size_t)(h * NTOK + i * HW + j)) * D + a;
        ksh[l] = g_K[gi];
        vsh[l] = g_V[gi];
    }
    __syncthreads();
    const int a = tid >> 3;
    const int b = (tid & 7) * 4;
    float4 acc = make_float4(0.f, 0.f, 0.f, 0.f);
    float kacc = 0.f;
    for (int i = 0; i < HW; i++) {
        float kv = ksh[i * D + a];
        float4 vv = *(const float4*)&vsh[i * D + b];
        acc.x += kv * vv.x; acc.y += kv * vv.y; acc.z += kv * vv.z; acc.w += kv * vv.w;
        *(float4*)&g_U[(((size_t)(h * HW + i)) * HW + j) * (D * D) + tid * 4] = acc;
        if (tid < 32) {
            kacc += ksh[i * D + tid];
            g_Kc[((h * HW + i) * HW + j) * D + tid] = kacc;
        }
    }
}

// ---------------- Kernel 3: column scan of g_Kc -> full 2D k integral --------
__global__ __launch_bounds__(256) void k_scan() {
    const int i = blockIdx.x;
    const int h = blockIdx.y;
    __shared__ float s[HW * D];
    float* row = g_Kc + (size_t)(h * HW + i) * HW * D;
    const int tid = threadIdx.x;
#pragma unroll
    for (int r = 0; r < 8; r++) s[tid + r * 256] = row[tid + r * 256];
    __syncthreads();
    if (tid < 32) {
        float acc = 0.f;
        for (int j = 0; j < HW; j++) {
            acc += s[j * D + tid];
            s[j * D + tid] = acc;
        }
    }
    __syncthreads();
#pragma unroll
    for (int r = 0; r < 8; r++) row[tid + r * 256] = s[tid + r * 256];
}

// ---------------- Kernel 4: windowed linear attention sweep ------------------
// block = (ii, window, head). Numerator via column sweep with depth-4 register
// prefetch, register-resident prefix (double-buffered SMEM mirror for events).
// Denominator via 4-corner reads of the full 2D k integral (no sweep).
__global__ __launch_bounds__(256, 3) void k_attn() {
    const int ii = blockIdx.x;
    const int win = blockIdx.y;
    const int h = blockIdx.z;
    const int r = (win == 0) ? 32 : (win == 1) ? 16 : 8;

    __shared__ float qsh[HW * D];        // 8 KB
    __shared__ float Msh[2][D * D];      // 8 KB
    __shared__ float numsh[HW * D];      // 8 KB
    __shared__ float densh[HW];

    const int tid = threadIdx.x;
    const int warp = tid >> 5, lane = tid & 31;

#pragma unroll
    for (int rr = 0; rr < 8; rr++) {
        int l = tid + rr * 256;
        qsh[l] = g_Q[((size_t)(h * NTOK + ii * HW)) * D + l];
        numsh[l] = 0.f;
    }

    const int x2 = min(ii + r, HW - 1);
    const int xl = ii - r - 1;
    const bool hasl = (xl >= 0);
    const float* Uh = g_U + ((size_t)(h * HW + x2)) * HW * (D * D);
    const float* Ul = g_U + ((size_t)(h * HW + max(xl, 0))) * HW * (D * D);

    // depth-4 register staging
    float4 sh[DEPTH], sl[DEPTH];
#pragma unroll
    for (int u = 0; u < DEPTH; u++) {
        sh[u] = *(const float4*)&Uh[(size_t)u * (D * D) + tid * 4];
        if (hasl) sl[u] = *(const float4*)&Ul[(size_t)u * (D * D) + tid * 4];
    }
    float4 mreg = make_float4(0.f, 0.f, 0.f, 0.f);

    for (int j0 = 0; j0 < HW; j0 += DEPTH) {
#pragma unroll
        for (int u = 0; u < DEPTH; u++) {
            const int j = j0 + u;
            const int cur = j & 1;
            // prefix update in registers; publish to SMEM buffer `cur`
            float4 dd = sh[u];
            if (hasl) { dd.x -= sl[u].x; dd.y -= sl[u].y; dd.z -= sl[u].z; dd.w -= sl[u].w; }
            mreg.x += dd.x; mreg.y += dd.y; mreg.z += dd.z; mreg.w += dd.w;
            *(float4*)&Msh[cur][tid * 4] = mreg;
            // prefetch j+DEPTH
            if (j + DEPTH < HW) {
                size_t off = (size_t)(j + DEPTH) * (D * D) + tid * 4;
                sh[u] = *(const float4*)&Uh[off];
                if (hasl) sl[u] = *(const float4*)&Ul[off];
            }
            __syncthreads();   // P(y=j) visible; fences events(j-2) vs write(j)

            // events: +1 at y2(jj)==j ; -1 at y1(jj)-1==j
            const int nplus = (j == HW - 1) ? (r + 1) : ((j >= r) ? 1 : 0);
            const int jjp0  = (j == HW - 1) ? (HW - 1 - r) : (j - r);
            const int hasminus = (j + r + 1 <= HW - 1) ? 1 : 0;
            const int nev = nplus + hasminus;
            for (int e = warp; e < nev; e += 8) {
                int jj; float sgn;
                if (e < nplus) { jj = jjp0 + e; sgn = 1.f; }
                else           { jj = j + r + 1; sgn = -1.f; }
                const float* qrow = &qsh[jj * D];
                const float* M = Msh[cur];
                float r0 = 0.f, r1 = 0.f, r2 = 0.f, r3 = 0.f;
#pragma unroll
                for (int a = 0; a < 8; a++) {
                    r0 += qrow[a]      * M[a * 32 + lane];
                    r1 += qrow[a + 8]  * M[(a + 8) * 32 + lane];
                    r2 += qrow[a + 16] * M[(a + 16) * 32 + lane];
                    r3 += qrow[a + 24] * M[(a + 24) * 32 + lane];
                }
                numsh[jj * D + lane] += sgn * ((r0 + r1) + (r2 + r3));
            }
        }
    }
    __syncthreads();

    // denominator: 4-corner reads of full 2D k integral (g_Kc after k_scan)
    const float* S2 = g_Kc + (size_t)(h * HW + x2) * HW * D;
    const float* Sl = g_Kc + (size_t)(h * HW + max(xl, 0)) * HW * D;
    for (int jj = warp; jj < HW; jj += 8) {
        const int y2 = min(jj + r, HW - 1);
        const int yl = jj - r - 1;
        float v = S2[y2 * D + lane];
        if (hasl) v -= Sl[y2 * D + lane];
        if (yl >= 0) {
            v -= S2[yl * D + lane];
            if (hasl) v += Sl[yl * D + lane];
        }
        float p = qsh[jj * D + lane] * v;
#pragma unroll
        for (int off = 16; off; off >>= 1) p += __shfl_xor_sync(0xffffffffu, p, off);
        if (lane == 0) densh[jj] = p;
    }
    __syncthreads();

    // write o = num/den to g_Cat
#pragma unroll
    for (int rr = 0; rr < 8; rr++) {
        int l = tid + rr * 256;
        int jj = l >> 5, e = l & 31;
        float o = numsh[l] / (densh[jj] + 1e-6f);
        g_Cat[(size_t)(ii * HW + jj) * INCDIM + win * DIMX + h * D + e] = o;
    }
}

// ---------------- Kernel 5: output GEMM + bias -------------------------------
// out[4096 x 256] = Cat[4096 x 768] @ wo + bo. Tile 64x128, 256 thr, 4x8/thr.
__global__ __launch_bounds__(256) void k_out(const float* __restrict__ wo,
                                             const float* __restrict__ bo,
                                             float* __restrict__ out) {
    __shared__ float As[32 * 64];    // [kk][m]
    __shared__ float Bs[32 * 128];   // [kk][n]
    const int row0 = blockIdx.x * 64;
    const int col0 = blockIdx.y * 128;
    const int tid = threadIdx.x;
    const int tx = tid & 15, ty = tid >> 4;

    float4 pa[2], pb[4];
#pragma unroll
    for (int i = 0; i < 2; i++) {
        int l = tid + i * 256;
        int m = l & 63, kq = l >> 6;
        pa[i] = *(const float4*)&g_Cat[(size_t)(row0 + m) * INCDIM + kq * 4];
    }
#pragma unroll
    for (int i = 0; i < 4; i++) {
        int l = tid + i * 256;
        int n4 = l & 31, kk = l >> 5;
        pb[i] = *(const float4*)&wo[(size_t)kk * DIMX + col0 + n4 * 4];
    }

    float2 acc[4][4] = {};
    for (int k0 = 0; k0 < INCDIM; k0 += 32) {
#pragma unroll
        for (int i = 0; i < 2; i++) {
            int l = tid + i * 256;
            int m = l & 63, kq = l >> 6;
            As[(kq * 4 + 0) * 64 + m] = pa[i].x;
            As[(kq * 4 + 1) * 64 + m] = pa[i].y;
            As[(kq * 4 + 2) * 64 + m] = pa[i].z;
            As[(kq * 4 + 3) * 64 + m] = pa[i].w;
        }
#pragma unroll
        for (int i = 0; i < 4; i++) {
            int l = tid + i * 256;
            int n4 = l & 31, kk = l >> 5;
            *(float4*)&Bs[kk * 128 + n4 * 4] = pb[i];
        }
        __syncthreads();
        if (k0 + 32 < INCDIM) {
#pragma unroll
            for (int i = 0; i < 2; i++) {
                int l = tid + i * 256;
                int m = l & 63, kq = l >> 6;
                pa[i] = *(const float4*)&g_Cat[(size_t)(row0 + m) * INCDIM + k0 + 32 + kq * 4];
            }
#pragma unroll
            for (int i = 0; i < 4; i++) {
                int l = tid + i * 256;
                int n4 = l & 31, kk = l >> 5;
                pb[i] = *(const float4*)&wo[(size_t)(k0 + 32 + kk) * DIMX + col0 + n4 * 4];
            }
        }
#pragma unroll
        for (int kk = 0; kk < 32; kk++) {
            float4 av = *(float4*)&As[kk * 64 + ty * 4];
            float4 b0 = *(float4*)&Bs[kk * 128 + tx * 8];
            float4 b1 = *(float4*)&Bs[kk * 128 + tx * 8 + 4];
            float a[4] = {av.x, av.y, av.z, av.w};
            float2 bv[4] = {{b0.x, b0.y}, {b0.z, b0.w}, {b1.x, b1.y}, {b1.z, b1.w}};
#pragma unroll
            for (int i = 0; i < 4; i++) {
                float2 a2 = {a[i], a[i]};
#pragma unroll
                for (int j = 0; j < 4; j++) ffma2(acc[i][j], a2, bv[j]);
            }
        }
        __syncthreads();
    }
#pragma unroll
    for (int i = 0; i < 4; i++) {
        int n = row0 + ty * 4 + i;
        int cb = col0 + tx * 8;
#pragma unroll
        for (int j = 0; j < 4; j++) {
            out[(size_t)n * DIMX + cb + j * 2]     = acc[i][j].x + bo[cb + j * 2];
            out[(size_t)n * DIMX + cb + j * 2 + 1] = acc[i][j].y + bo[cb + j * 2 + 1];
        }
    }
}

// ---------------- launch -----------------------------------------------------
extern "C" void kernel_launch(void* const* d_in, const int* in_sizes, int n_in,
                              void* d_out, int out_size) {
    const float* x  = (const float*)d_in[0];
    const float* wq = (const float*)d_in[1];
    const float* wk = (const float*)d_in[2];
    const float* wv = (const float*)d_in[3];
    const float* wo = (const float*)d_in[4];
    const float* bo = (const float*)d_in[5];
    float* out = (float*)d_out;

    k_qkv<<<dim3(NTOK / 64, INCDIM / 128), 128>>>(x, wq, wk, wv);
    k_integral<<<dim3(HW, HEADS), 256>>>();
    k_scan<<<dim3(HW, HEADS), 256>>>();
    k_attn<<<dim3(HW, 3, HEADS), 256>>>();
    k_out<<<dim3(NTOK / 64, DIMX / 128), 256>>>(wo, bo, out);
}